// round 8
// baseline (speedup 1.0000x reference)
#include <cuda_runtime.h>

// Problem constants
#define BATCH   1024
#define TSTEPS  256
#define UNITS   256
#define G4      1024   // 4*UNITS
#define NC      128
#define TB      8                 // batch rows per CTA
#define NCTA    (BATCH / TB)      // 128 CTAs
#define NTHREADS 512              // 16 warps -> 4 warps/SMSP

// smem pitches (floats)
#define ZP  12     // z_s[1024][12] : 16B-aligned float4 slots at +0/+4/+8
#define HP  12     // h_s[256][12]  : 16B-aligned rows for LDS.128

#define Z_FLOATS (G4 * ZP)        // 12288
#define H_FLOATS (UNITS * HP)     // 3072
#define SMEM_BYTES ((Z_FLOATS + H_FLOATS) * 4)   // 61440 B -> dynamic smem

// ---- packed fp32x2 helpers ----
__device__ __forceinline__ unsigned long long pack_dup(float x) {
    unsigned long long r;
    asm("mov.b64 %0, {%1, %1};" : "=l"(r) : "f"(x));
    return r;
}
__device__ __forceinline__ unsigned long long pack2(float lo, float hi) {
    unsigned long long r;
    asm("mov.b64 %0, {%1, %2};" : "=l"(r) : "f"(lo), "f"(hi));
    return r;
}
__device__ __forceinline__ void unpack2(unsigned long long v, float& lo, float& hi) {
    asm("mov.b64 {%0, %1}, %2;" : "=f"(lo), "=f"(hi) : "l"(v));
}
__device__ __forceinline__ void ffma2(unsigned long long& d,
                                      unsigned long long a,
                                      unsigned long long b) {
    asm("fma.rn.f32x2 %0, %1, %2, %0;" : "+l"(d) : "l"(a), "l"(b));
}

// ---- numerically safe fast activations (identical to passing version) ----
__device__ __forceinline__ float sigmoid_f(float x) {
    float e = __expf(-x);
    return __fdividef(1.0f, 1.0f + e);
}
__device__ __forceinline__ float tanh_f(float x) {
    float a = fabsf(x);
    float e = __expf(-2.0f * a);
    float t = 1.0f - __fdividef(2.0f * e, 1.0f + e);
    return copysignf(t, x);
}

__global__ __launch_bounds__(NTHREADS, 1)
void lstm_char_rnn_kernel(const int*   __restrict__ inp,   // [1024,256] int32
                          const float* __restrict__ Wk,    // kernel [128,1024]
                          const float* __restrict__ R,     // recurrent [256,1024]
                          const float* __restrict__ bias,  // [1024]
                          const float* __restrict__ Dw,    // dense_w [256,128]
                          const float* __restrict__ Db,    // dense_b [128]
                          float*       __restrict__ out)   // [1024,128]
{
    extern __shared__ float sm[];
    float* z_s = sm;                 // [1024][ZP]  (reused for logits at the end)
    float* h_s = sm + Z_FLOATS;      // [256][HP]; h_s[k*HP + r] = h(unit k, local row r)

    const int t  = threadIdx.x;      // 0..511
    const int b0 = blockIdx.x * TB;  // this CTA's batch rows [b0, b0+8)

    // matvec tile: thread owns 4 cols x 4 rows
    const int cg = t >> 1;           // column group 0..255
    const int j0 = 4 * cg;           // 4 z-columns j0..j0+3
    const int rg = t & 1;            // row group
    const int r0 = 4 * rg;           // 4 batch rows r0..r0+3 (local)

    // zero the h state
    for (int i = t; i < H_FLOATS; i += NTHREADS) h_s[i] = 0.0f;

    // gate-phase ownership: thread t owns unit u = t>>1, rows r0..r0+3
    const int u = cg;
    const float bi_ = bias[u];
    const float bf_ = bias[UNITS + u];
    const float bg_ = bias[2 * UNITS + u];
    const float bo_ = bias[3 * UNITS + u];

    float c[4];
#pragma unroll
    for (int j = 0; j < 4; j++) c[j] = 0.0f;

    const float4* R4 = reinterpret_cast<const float4*>(R);   // [256][256] float4
    const float4* W4 = reinterpret_cast<const float4*>(Wk);  // [128][256] float4

    // prefetch step-0 x_proj gather (rows r0..r0+3, cols j0..j0+3)
    float4 xa0, xa1, xb0, xb1;
    {
        int v0 = __ldg(&inp[(b0 + r0 + 0) * TSTEPS]);
        int v1 = __ldg(&inp[(b0 + r0 + 1) * TSTEPS]);
        int v2 = __ldg(&inp[(b0 + r0 + 2) * TSTEPS]);
        int v3 = __ldg(&inp[(b0 + r0 + 3) * TSTEPS]);
        xa0 = __ldg(&W4[v0 * (G4 / 4) + cg]);
        xa1 = __ldg(&W4[v1 * (G4 / 4) + cg]);
        xb0 = __ldg(&W4[v2 * (G4 / 4) + cg]);
        xb1 = __ldg(&W4[v3 * (G4 / 4) + cg]);
    }

    __syncthreads();

    for (int step = 0; step < TSTEPS; step++) {
        // ========== matvec: z[r0..r0+3][j0..j0+3] ==========
        // acc[p][q]: f32x2 = (z[row r0+2p], z[row r0+2p+1]) at column j0+q
        unsigned long long acc[2][2 * 2];
        acc[0][0] = pack2(xa0.x, xa1.x);
        acc[0][1] = pack2(xa0.y, xa1.y);
        acc[0][2] = pack2(xa0.z, xa1.z);
        acc[0][3] = pack2(xa0.w, xa1.w);
        acc[1][0] = pack2(xb0.x, xb1.x);
        acc[1][1] = pack2(xb0.y, xb1.y);
        acc[1][2] = pack2(xb0.z, xb1.z);
        acc[1][3] = pack2(xb0.w, xb1.w);

        // K-loop with rolling register prefetch of R
        float4 rv = __ldg(&R4[cg]);   // k = 0
#pragma unroll 4
        for (int k = 0; k < UNITS; k++) {
            float4 cur = rv;
            rv = __ldg(&R4[((k + 1) & (UNITS - 1)) * (G4 / 4) + cg]);  // prefetch k+1
            // h rows: even lanes rows 0-3, odd lanes rows 4-7 -> 1 wavefront
            ulonglong2 hp =
                *reinterpret_cast<const ulonglong2*>(&h_s[k * HP + r0]);
            unsigned long long rd0 = pack_dup(cur.x);
            unsigned long long rd1 = pack_dup(cur.y);
            unsigned long long rd2 = pack_dup(cur.z);
            unsigned long long rd3 = pack_dup(cur.w);
            ffma2(acc[0][0], hp.x, rd0);  ffma2(acc[1][0], hp.y, rd0);
            ffma2(acc[0][1], hp.x, rd1);  ffma2(acc[1][1], hp.y, rd1);
            ffma2(acc[0][2], hp.x, rd2);  ffma2(acc[1][2], hp.y, rd2);
            ffma2(acc[0][3], hp.x, rd3);  ffma2(acc[1][3], hp.y, rd3);
        }

        // prefetch next step's x_proj gather (latency hides under z-write+gates)
        {
            int s = (step + 1) & (TSTEPS - 1);
            int v0 = __ldg(&inp[(b0 + r0 + 0) * TSTEPS + s]);
            int v1 = __ldg(&inp[(b0 + r0 + 1) * TSTEPS + s]);
            int v2 = __ldg(&inp[(b0 + r0 + 2) * TSTEPS + s]);
            int v3 = __ldg(&inp[(b0 + r0 + 3) * TSTEPS + s]);
            xa0 = __ldg(&W4[v0 * (G4 / 4) + cg]);
            xa1 = __ldg(&W4[v1 * (G4 / 4) + cg]);
            xb0 = __ldg(&W4[v2 * (G4 / 4) + cg]);
            xb1 = __ldg(&W4[v3 * (G4 / 4) + cg]);
        }

        // write z pairs: z_s[col][row]
#pragma unroll
        for (int q = 0; q < 4; q++) {
            float* zc = &z_s[(j0 + q) * ZP + r0];
            *reinterpret_cast<unsigned long long*>(zc)     = acc[0][q];
            *reinterpret_cast<unsigned long long*>(zc + 2) = acc[1][q];
        }
        __syncthreads();

        // ========== gates: thread owns unit u, rows r0..r0+3 ==========
        float hv[4];
#pragma unroll
        for (int j = 0; j < 4; j++) {
            int r = r0 + j;
            float zi = z_s[u               * ZP + r] + bi_;
            float zf = z_s[(UNITS     + u) * ZP + r] + bf_;
            float zg = z_s[(2 * UNITS + u) * ZP + r] + bg_;
            float zo = z_s[(3 * UNITS + u) * ZP + r] + bo_;
            float ig = sigmoid_f(zi);
            float fg = sigmoid_f(zf);
            float gg = tanh_f(zg);
            float og = sigmoid_f(zo);
            float cn = fg * c[j] + ig * gg;
            c[j] = cn;
            hv[j] = og * tanh_f(cn);
        }
        // one STS.128 (16B aligned: byte offset = 48*u + 16*rg)
        *reinterpret_cast<float4*>(&h_s[u * HP + r0]) =
            make_float4(hv[0], hv[1], hv[2], hv[3]);
        __syncthreads();
    }

    // ========== dense: logits[r][col] = h_last[r] @ Dw + Db ==========
    {
        const int jc = t & (NC - 1);     // 0..127 output column
        const int rp = t >> 7;           // 0..3 row pair
        unsigned long long lg = pack_dup(__ldg(&Db[jc]));
        for (int uu = 0; uu < UNITS; uu++) {
            unsigned long long hp =
                *reinterpret_cast<const unsigned long long*>(&h_s[uu * HP + 2 * rp]);
            ffma2(lg, hp, pack_dup(__ldg(&Dw[uu * NC + jc])));
        }
        float l0, l1;
        unpack2(lg, l0, l1);
        z_s[(2 * rp)     * NC + jc] = l0;
        z_s[(2 * rp + 1) * NC + jc] = l1;
    }
    __syncthreads();

    // ========== softmax: first 8 warps, warp w handles local row w ==========
    if (t < 256) {
        const int w    = t >> 5;
        const int lane = t & 31;
        float v[4];
        float mx = -3.0e38f;
#pragma unroll
        for (int q = 0; q < 4; q++) {
            v[q] = z_s[w * NC + lane + 32 * q];
            mx = fmaxf(mx, v[q]);
        }
#pragma unroll
        for (int off = 16; off >= 1; off >>= 1)
            mx = fmaxf(mx, __shfl_xor_sync(0xffffffffu, mx, off));
        float sum = 0.0f;
#pragma unroll
        for (int q = 0; q < 4; q++) { v[q] = __expf(v[q] - mx); sum += v[q]; }
#pragma unroll
        for (int off = 16; off >= 1; off >>= 1)
            sum += __shfl_xor_sync(0xffffffffu, sum, off);
        float inv = 1.0f / sum;
#pragma unroll
        for (int q = 0; q < 4; q++)
            out[(b0 + w) * NC + lane + 32 * q] = v[q] * inv;
    }
}

extern "C" void kernel_launch(void* const* d_in, const int* in_sizes, int n_in,
                              void* d_out, int out_size) {
    const int*   inp  = (const int*)  d_in[0];  // inputs [1024,256]
    const float* Wk   = (const float*)d_in[1];  // kernel [128,1024]
    const float* R    = (const float*)d_in[2];  // recurrent_kernel [256,1024]
    const float* bias = (const float*)d_in[3];  // bias [1024]
    const float* Dw   = (const float*)d_in[4];  // dense_w [256,128]
    const float* Db   = (const float*)d_in[5];  // dense_b [128]
    float*       out  = (float*)d_out;          // [1024,128]

    cudaFuncSetAttribute(lstm_char_rnn_kernel,
                         cudaFuncAttributeMaxDynamicSharedMemorySize, SMEM_BYTES);

    lstm_char_rnn_kernel<<<NCTA, NTHREADS, SMEM_BYTES>>>(inp, Wk, R, bias, Dw, Db, out);
}